// round 16
// baseline (speedup 1.0000x reference)
#include <cuda_runtime.h>
#include <cuda_fp16.h>
#include <cstdint>

// FAVOR+ attention via mma.sync m16n8k16 fp16 (fp32 accum) + ldmatrix(+trans).
// 256-thread CTAs, 2 CTAs/SM. B=4, L=4096, D=1024, H=16 x d=64, m=256.
// favor_q: each warp accumulates full k=256 GEMM3 in registers (no partial
// exchange); favor_k: natural layouts + ldmatrix.trans.

namespace {
constexpr int L_ = 4096, D_ = 1024;
constexpr float SCALE = 0.17677669529663687f, SC2 = SCALE * SCALE;
constexpr float CEPS = 1e-4f, INVSQM = 0.0625f;
// favor_k smem (uint32 word offsets)
constexpr int KW = 0;          // W    [256 f][36]
constexpr int KX = 9216;       // K    [64 l][36]
constexpr int KVo = 11520;     // Vaug [64 l][36]  cols 64..71 = aug
constexpr int KP = 13824;      // k'   [64 l][132]
constexpr int KH = 22272;      // eb[64] fp32
constexpr int KFL = 22336;     // 89344 B
// favor_q smem
constexpr int QW = 0;          // W    [256 f][36]
constexpr int QT = 9216;       // Q    [128 l][36]
constexpr int QKV = 13824;     // KV^T [72 d'][132]
constexpr int QFL = 23328;     // 93312 B (x2 CTA = 186.6 KB)
}

__device__ float g_kv[64 * 256 * 72];   // [bh][f][d'(64=ksum)]
__device__ unsigned g_min_ss;

__device__ __forceinline__ uint32_t h2(float a, float b) {
    __half2 h = __floats2half2_rn(a, b);
    return *reinterpret_cast<uint32_t*>(&h);
}
__device__ __forceinline__ void mma16(float* c, const uint32_t* a, const uint32_t* b) {
    asm volatile(
        "mma.sync.aligned.m16n8k16.row.col.f32.f16.f16.f32 "
        "{%0,%1,%2,%3},{%4,%5,%6,%7},{%8,%9},{%0,%1,%2,%3};"
        : "+f"(c[0]), "+f"(c[1]), "+f"(c[2]), "+f"(c[3])
        : "r"(a[0]), "r"(a[1]), "r"(a[2]), "r"(a[3]), "r"(b[0]), "r"(b[1]));
}
__device__ __forceinline__ void ldsm4(uint32_t* r, uint32_t a) {
    asm volatile("ldmatrix.sync.aligned.m8n8.x4.shared.b16 {%0,%1,%2,%3}, [%4];"
        : "=r"(r[0]), "=r"(r[1]), "=r"(r[2]), "=r"(r[3]) : "r"(a));
}
__device__ __forceinline__ void ldsm2(uint32_t* r, uint32_t a) {
    asm volatile("ldmatrix.sync.aligned.m8n8.x2.shared.b16 {%0,%1}, [%2];"
        : "=r"(r[0]), "=r"(r[1]) : "r"(a));
}
__device__ __forceinline__ void ldsm4t(uint32_t* r, uint32_t a) {
    asm volatile("ldmatrix.sync.aligned.m8n8.x4.trans.shared.b16 {%0,%1,%2,%3}, [%4];"
        : "=r"(r[0]), "=r"(r[1]), "=r"(r[2]), "=r"(r[3]) : "r"(a));
}
__device__ __forceinline__ void ldsm2t(uint32_t* r, uint32_t a) {
    asm volatile("ldmatrix.sync.aligned.m8n8.x2.trans.shared.b16 {%0,%1}, [%2];"
        : "=r"(r[0]), "=r"(r[1]) : "r"(a));
}

// ---------------------------------------------------------------------------
__global__ void init_kernel() { g_min_ss = 0x7F800000u; }

__global__ __launch_bounds__(256) void min_kernel(const float* __restrict__ Kp) {
    int t = threadIdx.x;
    {   // zero scratch
        size_t tid = (size_t)blockIdx.x * 256 + t;
        constexpr size_t n = (size_t)64 * 256 * 72;
        for (size_t i = tid; i < n; i += (size_t)gridDim.x * 256) g_kv[i] = 0.f;
    }
    float mn = 3.4028235e38f;
#pragma unroll
    for (int it = 0; it < 16; ++it) {
        size_t ch = (size_t)blockIdx.x * 256 + it * 16 + (t >> 4);
        float4 v4 = *reinterpret_cast<const float4*>(Kp + ch * 64 + (t & 15) * 4);
        float ss = v4.x * v4.x + v4.y * v4.y + v4.z * v4.z + v4.w * v4.w;
        ss += __shfl_xor_sync(~0u, ss, 8); ss += __shfl_xor_sync(~0u, ss, 4);
        ss += __shfl_xor_sync(~0u, ss, 2); ss += __shfl_xor_sync(~0u, ss, 1);
        mn = fminf(mn, ss);
    }
    mn = fminf(mn, __shfl_xor_sync(~0u, mn, 16));
    __shared__ float wmin[8];
    if ((t & 31) == 0) wmin[t >> 5] = mn;
    __syncthreads();
    if (t < 8) {
        float m2 = wmin[t];
        m2 = fminf(m2, __shfl_xor_sync(0xffu, m2, 4));
        m2 = fminf(m2, __shfl_xor_sync(0xffu, m2, 2));
        m2 = fminf(m2, __shfl_xor_sync(0xffu, m2, 1));
        if (t == 0) atomicMin(&g_min_ss, __float_as_uint(m2));
    }
}

// ---------------------------------------------------------------------------
__global__ __launch_bounds__(256, 2) void favor_k(
    const float* __restrict__ K_, const float* __restrict__ V_,
    const float* __restrict__ W_) {
    extern __shared__ float s[];
    uint32_t* su = reinterpret_cast<uint32_t*>(s);
    const uint32_t sb = (uint32_t)__cvta_generic_to_shared(s);
    const int t = threadIdx.x, w = t >> 5, lane = t & 31;
    const int qrow = lane >> 2, qc = lane & 3;
    const int bh = blockIdx.x, bb = bh >> 4, hh = bh & 15;
#pragma unroll
    for (int i = 0; i < 16; ++i) {   // W natural k-order
        int idx = t + i * 256, f = idx >> 4, c4 = idx & 15;
        float4 wv = *reinterpret_cast<const float4*>(W_ + f * 64 + c4 * 4);
        *reinterpret_cast<uint2*>(su + KW + f * 36 + 2 * c4) =
            make_uint2(h2(wv.x, wv.y), h2(wv.z, wv.w));
    }
    su[KVo + (t & 63) * 36 + 32 + (t >> 6)] = ((t >> 6) == 0) ? h2(1.f, 0.f) : 0u;
    const float stab = -0.5f * SC2 * __uint_as_float(g_min_ss);
    float kvacc[2][9][4] = {};
    __syncthreads();
    const int mb = (w >> 2) * 32, nb = (w & 3) * 32;
    const int fb = w * 16;
    const int lrow = lane & 15;
    const int khi = (lane >> 4) * 16;
    const int bko = (lane & 8) ? 16 : 0;
    const int brow = (lane & 7) + ((lane & 16) ? 8 : 0);
    const uint32_t aA = sb + (KX + (mb + lrow) * 36) * 4 + khi;
    const int a2row = (lane & 7) + ((lane & 16) ? 8 : 0);
    const int a2foff = (lane & 8) ? 8 : 0;
    const uint32_t aP = sb + (KP + a2row * 132) * 4 + (fb + a2foff) * 2;
    const uint32_t bV = sb + (KVo + lrow * 36) * 4 + ((lane & 16) ? 16 : 0);
    const uint32_t bV8 = sb + (KVo + lrow * 36) * 4 + 128;

    for (int ti = 0; ti < 8; ++ti) {
        const int l0 = ((int)blockIdx.y * 8 + ti) * 64;
#pragma unroll
        for (int i = 0; i < 4; ++i) {
            int idx = t + i * 256, l = idx >> 4, c4 = idx & 15;
            size_t off = ((size_t)(bb * L_ + l0 + l)) * D_ + hh * 64 + c4 * 4;
            float4 kk = *reinterpret_cast<const float4*>(K_ + off);
            *reinterpret_cast<uint2*>(su + KX + l * 36 + 2 * c4) =
                make_uint2(h2(kk.x, kk.y), h2(kk.z, kk.w));
            float ss = kk.x * kk.x + kk.y * kk.y + kk.z * kk.z + kk.w * kk.w;
            ss += __shfl_xor_sync(~0u, ss, 1);
            ss += __shfl_xor_sync(~0u, ss, 2);
            ss += __shfl_xor_sync(~0u, ss, 4);
            ss += __shfl_xor_sync(~0u, ss, 8);
            if ((t & 15) == 0) s[KH + l] = fmaf(-0.5f * SC2, ss, -stab);
            float4 vv = *reinterpret_cast<const float4*>(V_ + off);
            *reinterpret_cast<uint2*>(su + KVo + l * 36 + 2 * c4) =
                make_uint2(h2(vv.x, vv.y), h2(vv.z, vv.w));
        }
        __syncthreads();
#pragma unroll
        for (int h = 0; h < 2; ++h) {
            const uint32_t bW = sb + (KW + (h * 128 + nb + brow) * 36) * 4 + bko;
            float c[2][4][4] = {};
#pragma unroll
            for (int ks = 0; ks < 4; ++ks) {
                uint32_t a0[4], a1[4], b0[4], b1[4];
                ldsm4(a0, aA + ks * 32);
                ldsm4(a1, aA + 16 * 144 + ks * 32);
                ldsm4(b0, bW + ks * 32);
                ldsm4(b1, bW + 2304 + ks * 32);
                mma16(c[0][0], a0, b0); mma16(c[0][1], a0, b0 + 2);
                mma16(c[0][2], a0, b1); mma16(c[0][3], a0, b1 + 2);
                mma16(c[1][0], a1, b0); mma16(c[1][1], a1, b0 + 2);
                mma16(c[1][2], a1, b1); mma16(c[1][3], a1, b1 + 2);
            }
#pragma unroll
            for (int mi = 0; mi < 2; ++mi) {
                int r0 = mb + mi * 16 + qrow;
                float eb0 = s[KH + r0], eb1 = s[KH + r0 + 8];
#pragma unroll
                for (int ni = 0; ni < 4; ++ni) {
                    int wcol = h * 64 + (nb >> 1) + ni * 4 + qc;
                    su[KP + r0 * 132 + wcol] =
                        h2(INVSQM * (__expf(fmaf(SCALE, c[mi][ni][0], eb0)) + CEPS),
                           INVSQM * (__expf(fmaf(SCALE, c[mi][ni][1], eb0)) + CEPS));
                    su[KP + (r0 + 8) * 132 + wcol] =
                        h2(INVSQM * (__expf(fmaf(SCALE, c[mi][ni][2], eb1)) + CEPS),
                           INVSQM * (__expf(fmaf(SCALE, c[mi][ni][3], eb1)) + CEPS));
                }
            }
        }
        __syncthreads();
#pragma unroll
        for (int ks = 0; ks < 4; ++ks) {
            uint32_t a0[4], a1[4], bv0[4], bv1[4], bv2[4], bv3[4], bv8[2];
            ldsm4t(a0, aP + ks * 8448);
            ldsm4t(a1, aP + 256 + ks * 8448);
            ldsm4t(bv0, bV + ks * 2304);
            ldsm4t(bv1, bV + 32 + ks * 2304);
            ldsm4t(bv2, bV + 64 + ks * 2304);
            ldsm4t(bv3, bV + 96 + ks * 2304);
            ldsm2t(bv8, bV8 + ks * 2304);
            mma16(kvacc[0][0], a0, bv0); mma16(kvacc[0][1], a0, bv0 + 2);
            mma16(kvacc[0][2], a0, bv1); mma16(kvacc[0][3], a0, bv1 + 2);
            mma16(kvacc[0][4], a0, bv2); mma16(kvacc[0][5], a0, bv2 + 2);
            mma16(kvacc[0][6], a0, bv3); mma16(kvacc[0][7], a0, bv3 + 2);
            mma16(kvacc[0][8], a0, bv8);
            mma16(kvacc[1][0], a1, bv0); mma16(kvacc[1][1], a1, bv0 + 2);
            mma16(kvacc[1][2], a1, bv1); mma16(kvacc[1][3], a1, bv1 + 2);
            mma16(kvacc[1][4], a1, bv2); mma16(kvacc[1][5], a1, bv2 + 2);
            mma16(kvacc[1][6], a1, bv3); mma16(kvacc[1][7], a1, bv3 + 2);
            mma16(kvacc[1][8], a1, bv8);
        }
        __syncthreads();
    }
    float* g = g_kv + (size_t)bh * 256 * 72;
#pragma unroll
    for (int h = 0; h < 2; ++h)
#pragma unroll
        for (int ni = 0; ni < 9; ++ni) {
            int f0 = h * 128 + fb + qrow, d0 = ni * 8 + qc * 2;
            atomicAdd(g + f0 * 72 + d0, kvacc[h][ni][0]);
            atomicAdd(g + f0 * 72 + d0 + 1, kvacc[h][ni][1]);
            atomicAdd(g + (f0 + 8) * 72 + d0, kvacc[h][ni][2]);
            atomicAdd(g + (f0 + 8) * 72 + d0 + 1, kvacc[h][ni][3]);
        }
}

// ---------------------------------------------------------------------------
// favor_q: 128-row tiles, 8 warps x 16 rows. Each warp runs both f-halves
// sequentially, accumulating out[16,72] fully in registers. No partials, no
// smem exchange; denominator via shfl.
// ---------------------------------------------------------------------------
__global__ __launch_bounds__(256, 2) void favor_q(
    const float* __restrict__ Q_, const float* __restrict__ W_,
    float* __restrict__ O_) {
    extern __shared__ float s[];
    uint32_t* su = reinterpret_cast<uint32_t*>(s);
    __half* sh16 = reinterpret_cast<__half*>(s);
    const uint32_t sb = (uint32_t)__cvta_generic_to_shared(s);
    const int t = threadIdx.x, w = t >> 5, lane = t & 31;
    const int qrow = lane >> 2, qc = lane & 3;
    const int bh = blockIdx.x, bb = bh >> 4, hh = bh & 15;
#pragma unroll
    for (int i = 0; i < 16; ++i) {
        int idx = t + i * 256, f = idx >> 4, c4 = idx & 15;
        float4 wv = *reinterpret_cast<const float4*>(W_ + f * 64 + c4 * 4);
        *reinterpret_cast<uint2*>(su + QW + f * 36 + 2 * c4) =
            make_uint2(h2(wv.x, wv.y), h2(wv.z, wv.w));
    }
    {   // KV^T [d'][f] fp16, natural f order
        const float* g = g_kv + (size_t)bh * 256 * 72;
        for (int i = t; i < 256 * 72; i += 256) {
            int f = i / 72, d = i - f * 72;
            sh16[(QKV + d * 132) * 2 + f] = __float2half(g[i]);
        }
    }
    __syncthreads();
    const int ms = w * 16;
    const int lrow = lane & 15;
    const int khi = (lane >> 4) * 16;
    const int bko = (lane & 8) ? 16 : 0;
    const int brow = (lane & 7) + ((lane & 16) ? 8 : 0);
    const uint32_t aQ = sb + (QT + (ms + lrow) * 36) * 4 + khi;
    const uint32_t bW0 = sb + (QW + brow * 36) * 4 + bko;
    const uint32_t bK0 = sb + (QKV + brow * 132) * 4 + bko;
    const uint32_t bK80 = sb + (QKV + (64 + (lane & 7)) * 132) * 4 + bko;

    for (int ti = 0; ti < 8; ++ti) {
        const int l0 = ((int)blockIdx.y * 8 + ti) * 128;
#pragma unroll
        for (int i = 0; i < 8; ++i) {
            int idx = t + i * 256, l = idx >> 4, c4 = idx & 15;
            size_t off = ((size_t)(bb * L_ + l0 + l)) * D_ + hh * 64 + c4 * 4;
            float4 qq = *reinterpret_cast<const float4*>(Q_ + off);
            *reinterpret_cast<uint2*>(su + QT + l * 36 + 2 * c4) =
                make_uint2(h2(qq.x, qq.y), h2(qq.z, qq.w));
        }
        __syncthreads();
        float o[9][4] = {};
#pragma unroll
        for (int fg = 0; fg < 2; ++fg) {
            const uint32_t bW = bW0 + fg * 18432;       // 128 rows * 36 w * 4 B
            const uint32_t bK = bK0 + fg * 256;         // 128 halfs = 256 B
            const uint32_t bK8 = bK80 + fg * 256;
            // ---- GEMM1: S(16m x 128n), n-range fg*128 ----
            float c[16][4] = {};
#pragma unroll
            for (int ks = 0; ks < 4; ++ks) {
                uint32_t a2[4];
                ldsm4(a2, aQ + ks * 32);
#pragma unroll
                for (int p = 0; p < 8; ++p) {
                    uint32_t bp[4];
                    ldsm4(bp, bW + p * 2304 + ks * 32);
                    mma16(c[2 * p], a2, bp);
                    mma16(c[2 * p + 1], a2, bp + 2);
                }
            }
            // ---- epilogue: exp + pack -> fp16 A-frags ----
            uint32_t cu[8][4];
#pragma unroll
            for (int j = 0; j < 8; ++j) {
                float v00 = INVSQM * (__expf(SCALE * c[2 * j][0]) + CEPS);
                float v01 = INVSQM * (__expf(SCALE * c[2 * j][1]) + CEPS);
                float v02 = INVSQM * (__expf(SCALE * c[2 * j][2]) + CEPS);
                float v03 = INVSQM * (__expf(SCALE * c[2 * j][3]) + CEPS);
                float v10 = INVSQM * (__expf(SCALE * c[2 * j + 1][0]) + CEPS);
                float v11 = INVSQM * (__expf(SCALE * c[2 * j + 1][1]) + CEPS);
                float v12 = INVSQM * (__expf(SCALE * c[2 * j + 1][2]) + CEPS);
                float v13 = INVSQM * (__expf(SCALE * c[2 * j + 1][3]) + CEPS);
                cu[j][0] = h2(v00, v01);
                cu[j][1] = h2(v02, v03);
                cu[j][2] = h2(v10, v11);
                cu[j][3] = h2(v12, v13);
            }
            // ---- GEMM3: out += q'_half x KV^T_half ----
#pragma unroll
            for (int j = 0; j < 8; ++j) {
                uint32_t bv0[4], bv1[4], bv2[4], bv3[4], bv8[2];
                ldsm4(bv0, bK + j * 32);
                ldsm4(bv1, bK + 8448 + j * 32);
                ldsm4(bv2, bK + 16896 + j * 32);
                ldsm4(bv3, bK + 25344 + j * 32);
                ldsm2(bv8, bK8 + j * 32);
                mma16(o[0], cu[j], bv0); mma16(o[1], cu[j], bv0 + 2);
                mma16(o[2], cu[j], bv1); mma16(o[3], cu[j], bv1 + 2);
                mma16(o[4], cu[j], bv2); mma16(o[5], cu[j], bv2 + 2);
                mma16(o[6], cu[j], bv3); mma16(o[7], cu[j], bv3 + 2);
                mma16(o[8], cu[j], bv8);
            }
        }
        // ---- finish: denominator (col 64 = o[8] @ qc==0), divide, store ----
        float den0 = __shfl_sync(~0u, o[8][0], lane & ~3);
        float den1 = __shfl_sync(~0u, o[8][2], lane & ~3);
        if (fabsf(den0) <= CEPS) den0 += 2.f * CEPS;
        if (fabsf(den1) <= CEPS) den1 += 2.f * CEPS;
        float inv0 = 1.f / den0, inv1 = 1.f / den1;
        int r0 = ms + qrow;
        float* op0 = O_ + ((size_t)(bb * L_ + l0 + r0)) * D_ + hh * 64;
        float* op1 = op0 + 8 * D_;
#pragma unroll
        for (int ni = 0; ni < 8; ++ni) {
            int col = ni * 8 + 2 * qc;
            *reinterpret_cast<float2*>(op0 + col) =
                make_float2(o[ni][0] * inv0, o[ni][1] * inv0);
            *reinterpret_cast<float2*>(op1 + col) =
                make_float2(o[ni][2] * inv1, o[ni][3] * inv1);
        }
        __syncthreads();
    }
}

// ---------------------------------------------------------------------------
extern "C" void kernel_launch(void* const* d_in, const int* in_sizes, int n_in,
                              void* d_out, int out_size) {
    const float* q = (const float*)d_in[0];
    const float* k = (const float*)d_in[1];
    const float* v = (const float*)d_in[2];
    const float* w = (const float*)d_in[3];
    float* out = (float*)d_out;

    cudaFuncSetAttribute(favor_k, cudaFuncAttributeMaxDynamicSharedMemorySize, KFL * 4);
    cudaFuncSetAttribute(favor_q, cudaFuncAttributeMaxDynamicSharedMemorySize, QFL * 4);

    init_kernel<<<1, 1>>>();
    min_kernel<<<1024, 256>>>(k);
    favor_k<<<dim3(64, 8), 256, KFL * 4>>>(k, v, w);
    favor_q<<<dim3(64, 4), 256, QFL * 4>>>(q, w, out);
}

// round 17
// speedup vs baseline: 1.4744x; 1.4744x over previous
#include <cuda_runtime.h>
#include <cuda_fp16.h>
#include <cstdint>

// FAVOR+ attention via mma.sync m16n8k16 fp16 (fp32 accum) + ldmatrix(+trans).
// 256-thread CTAs, 2 CTAs/SM. B=4, L=4096, D=1024, H=16 x d=64, m=256.
// favor_q: 128-row tiles, per-warp full-k register accumulation, f processed
// in four 64-wide quarters to bound register liveness (no smem exchange).

namespace {
constexpr int L_ = 4096, D_ = 1024;
constexpr float SCALE = 0.17677669529663687f, SC2 = SCALE * SCALE;
constexpr float CEPS = 1e-4f, INVSQM = 0.0625f;
// favor_k smem (uint32 word offsets)
constexpr int KW = 0;          // W    [256 f][36]
constexpr int KX = 9216;       // K    [64 l][36]
constexpr int KVo = 11520;     // Vaug [64 l][36]  cols 64..71 = aug
constexpr int KP = 13824;      // k'   [64 l][132]
constexpr int KH = 22272;      // eb[64] fp32
constexpr int KFL = 22336;     // 89344 B
// favor_q smem
constexpr int QW = 0;          // W    [256 f][36]
constexpr int QT = 9216;       // Q    [128 l][36]
constexpr int QKV = 13824;     // KV^T [72 d'][132]
constexpr int QFL = 23328;     // 93312 B (x2 CTA = 186.6 KB)
}

__device__ float g_kv[64 * 256 * 72];   // [bh][f][d'(64=ksum)]
__device__ unsigned g_min_ss;

__device__ __forceinline__ uint32_t h2(float a, float b) {
    __half2 h = __floats2half2_rn(a, b);
    return *reinterpret_cast<uint32_t*>(&h);
}
__device__ __forceinline__ void mma16(float* c, const uint32_t* a, const uint32_t* b) {
    asm volatile(
        "mma.sync.aligned.m16n8k16.row.col.f32.f16.f16.f32 "
        "{%0,%1,%2,%3},{%4,%5,%6,%7},{%8,%9},{%0,%1,%2,%3};"
        : "+f"(c[0]), "+f"(c[1]), "+f"(c[2]), "+f"(c[3])
        : "r"(a[0]), "r"(a[1]), "r"(a[2]), "r"(a[3]), "r"(b[0]), "r"(b[1]));
}
__device__ __forceinline__ void ldsm4(uint32_t* r, uint32_t a) {
    asm volatile("ldmatrix.sync.aligned.m8n8.x4.shared.b16 {%0,%1,%2,%3}, [%4];"
        : "=r"(r[0]), "=r"(r[1]), "=r"(r[2]), "=r"(r[3]) : "r"(a));
}
__device__ __forceinline__ void ldsm2(uint32_t* r, uint32_t a) {
    asm volatile("ldmatrix.sync.aligned.m8n8.x2.shared.b16 {%0,%1}, [%2];"
        : "=r"(r[0]), "=r"(r[1]) : "r"(a));
}
__device__ __forceinline__ void ldsm4t(uint32_t* r, uint32_t a) {
    asm volatile("ldmatrix.sync.aligned.m8n8.x4.trans.shared.b16 {%0,%1,%2,%3}, [%4];"
        : "=r"(r[0]), "=r"(r[1]), "=r"(r[2]), "=r"(r[3]) : "r"(a));
}
__device__ __forceinline__ void ldsm2t(uint32_t* r, uint32_t a) {
    asm volatile("ldmatrix.sync.aligned.m8n8.x2.trans.shared.b16 {%0,%1}, [%2];"
        : "=r"(r[0]), "=r"(r[1]) : "r"(a));
}

// ---------------------------------------------------------------------------
__global__ void init_kernel() { g_min_ss = 0x7F800000u; }

__global__ __launch_bounds__(256) void min_kernel(const float* __restrict__ Kp) {
    int t = threadIdx.x;
    {   // zero scratch
        size_t tid = (size_t)blockIdx.x * 256 + t;
        constexpr size_t n = (size_t)64 * 256 * 72;
        for (size_t i = tid; i < n; i += (size_t)gridDim.x * 256) g_kv[i] = 0.f;
    }
    float mn = 3.4028235e38f;
#pragma unroll
    for (int it = 0; it < 16; ++it) {
        size_t ch = (size_t)blockIdx.x * 256 + it * 16 + (t >> 4);
        float4 v4 = *reinterpret_cast<const float4*>(Kp + ch * 64 + (t & 15) * 4);
        float ss = v4.x * v4.x + v4.y * v4.y + v4.z * v4.z + v4.w * v4.w;
        ss += __shfl_xor_sync(~0u, ss, 8); ss += __shfl_xor_sync(~0u, ss, 4);
        ss += __shfl_xor_sync(~0u, ss, 2); ss += __shfl_xor_sync(~0u, ss, 1);
        mn = fminf(mn, ss);
    }
    mn = fminf(mn, __shfl_xor_sync(~0u, mn, 16));
    __shared__ float wmin[8];
    if ((t & 31) == 0) wmin[t >> 5] = mn;
    __syncthreads();
    if (t < 8) {
        float m2 = wmin[t];
        m2 = fminf(m2, __shfl_xor_sync(0xffu, m2, 4));
        m2 = fminf(m2, __shfl_xor_sync(0xffu, m2, 2));
        m2 = fminf(m2, __shfl_xor_sync(0xffu, m2, 1));
        if (t == 0) atomicMin(&g_min_ss, __float_as_uint(m2));
    }
}

// ---------------------------------------------------------------------------
__global__ __launch_bounds__(256, 2) void favor_k(
    const float* __restrict__ K_, const float* __restrict__ V_,
    const float* __restrict__ W_) {
    extern __shared__ float s[];
    uint32_t* su = reinterpret_cast<uint32_t*>(s);
    const uint32_t sb = (uint32_t)__cvta_generic_to_shared(s);
    const int t = threadIdx.x, w = t >> 5, lane = t & 31;
    const int qrow = lane >> 2, qc = lane & 3;
    const int bh = blockIdx.x, bb = bh >> 4, hh = bh & 15;
#pragma unroll
    for (int i = 0; i < 16; ++i) {   // W natural k-order
        int idx = t + i * 256, f = idx >> 4, c4 = idx & 15;
        float4 wv = *reinterpret_cast<const float4*>(W_ + f * 64 + c4 * 4);
        *reinterpret_cast<uint2*>(su + KW + f * 36 + 2 * c4) =
            make_uint2(h2(wv.x, wv.y), h2(wv.z, wv.w));
    }
    su[KVo + (t & 63) * 36 + 32 + (t >> 6)] = ((t >> 6) == 0) ? h2(1.f, 0.f) : 0u;
    const float stab = -0.5f * SC2 * __uint_as_float(g_min_ss);
    float kvacc[2][9][4] = {};
    __syncthreads();
    const int mb = (w >> 2) * 32, nb = (w & 3) * 32;
    const int fb = w * 16;
    const int lrow = lane & 15;
    const int khi = (lane >> 4) * 16;
    const int bko = (lane & 8) ? 16 : 0;
    const int brow = (lane & 7) + ((lane & 16) ? 8 : 0);
    const uint32_t aA = sb + (KX + (mb + lrow) * 36) * 4 + khi;
    const int a2row = (lane & 7) + ((lane & 16) ? 8 : 0);
    const int a2foff = (lane & 8) ? 8 : 0;
    const uint32_t aP = sb + (KP + a2row * 132) * 4 + (fb + a2foff) * 2;
    const uint32_t bV = sb + (KVo + lrow * 36) * 4 + ((lane & 16) ? 16 : 0);
    const uint32_t bV8 = sb + (KVo + lrow * 36) * 4 + 128;

    for (int ti = 0; ti < 8; ++ti) {
        const int l0 = ((int)blockIdx.y * 8 + ti) * 64;
#pragma unroll
        for (int i = 0; i < 4; ++i) {
            int idx = t + i * 256, l = idx >> 4, c4 = idx & 15;
            size_t off = ((size_t)(bb * L_ + l0 + l)) * D_ + hh * 64 + c4 * 4;
            float4 kk = *reinterpret_cast<const float4*>(K_ + off);
            *reinterpret_cast<uint2*>(su + KX + l * 36 + 2 * c4) =
                make_uint2(h2(kk.x, kk.y), h2(kk.z, kk.w));
            float ss = kk.x * kk.x + kk.y * kk.y + kk.z * kk.z + kk.w * kk.w;
            ss += __shfl_xor_sync(~0u, ss, 1);
            ss += __shfl_xor_sync(~0u, ss, 2);
            ss += __shfl_xor_sync(~0u, ss, 4);
            ss += __shfl_xor_sync(~0u, ss, 8);
            if ((t & 15) == 0) s[KH + l] = fmaf(-0.5f * SC2, ss, -stab);
            float4 vv = *reinterpret_cast<const float4*>(V_ + off);
            *reinterpret_cast<uint2*>(su + KVo + l * 36 + 2 * c4) =
                make_uint2(h2(vv.x, vv.y), h2(vv.z, vv.w));
        }
        __syncthreads();
#pragma unroll
        for (int h = 0; h < 2; ++h) {
            const uint32_t bW = sb + (KW + (h * 128 + nb + brow) * 36) * 4 + bko;
            float c[2][4][4] = {};
#pragma unroll
            for (int ks = 0; ks < 4; ++ks) {
                uint32_t a0[4], a1[4], b0[4], b1[4];
                ldsm4(a0, aA + ks * 32);
                ldsm4(a1, aA + 16 * 144 + ks * 32);
                ldsm4(b0, bW + ks * 32);
                ldsm4(b1, bW + 2304 + ks * 32);
                mma16(c[0][0], a0, b0); mma16(c[0][1], a0, b0 + 2);
                mma16(c[0][2], a0, b1); mma16(c[0][3], a0, b1 + 2);
                mma16(c[1][0], a1, b0); mma16(c[1][1], a1, b0 + 2);
                mma16(c[1][2], a1, b1); mma16(c[1][3], a1, b1 + 2);
            }
#pragma unroll
            for (int mi = 0; mi < 2; ++mi) {
                int r0 = mb + mi * 16 + qrow;
                float eb0 = s[KH + r0], eb1 = s[KH + r0 + 8];
#pragma unroll
                for (int ni = 0; ni < 4; ++ni) {
                    int wcol = h * 64 + (nb >> 1) + ni * 4 + qc;
                    su[KP + r0 * 132 + wcol] =
                        h2(INVSQM * (__expf(fmaf(SCALE, c[mi][ni][0], eb0)) + CEPS),
                           INVSQM * (__expf(fmaf(SCALE, c[mi][ni][1], eb0)) + CEPS));
                    su[KP + (r0 + 8) * 132 + wcol] =
                        h2(INVSQM * (__expf(fmaf(SCALE, c[mi][ni][2], eb1)) + CEPS),
                           INVSQM * (__expf(fmaf(SCALE, c[mi][ni][3], eb1)) + CEPS));
                }
            }
        }
        __syncthreads();
#pragma unroll
        for (int ks = 0; ks < 4; ++ks) {
            uint32_t a0[4], a1[4], bv0[4], bv1[4], bv2[4], bv3[4], bv8[2];
            ldsm4t(a0, aP + ks * 8448);
            ldsm4t(a1, aP + 256 + ks * 8448);
            ldsm4t(bv0, bV + ks * 2304);
            ldsm4t(bv1, bV + 32 + ks * 2304);
            ldsm4t(bv2, bV + 64 + ks * 2304);
            ldsm4t(bv3, bV + 96 + ks * 2304);
            ldsm2t(bv8, bV8 + ks * 2304);
            mma16(kvacc[0][0], a0, bv0); mma16(kvacc[0][1], a0, bv0 + 2);
            mma16(kvacc[0][2], a0, bv1); mma16(kvacc[0][3], a0, bv1 + 2);
            mma16(kvacc[0][4], a0, bv2); mma16(kvacc[0][5], a0, bv2 + 2);
            mma16(kvacc[0][6], a0, bv3); mma16(kvacc[0][7], a0, bv3 + 2);
            mma16(kvacc[0][8], a0, bv8);
            mma16(kvacc[1][0], a1, bv0); mma16(kvacc[1][1], a1, bv0 + 2);
            mma16(kvacc[1][2], a1, bv1); mma16(kvacc[1][3], a1, bv1 + 2);
            mma16(kvacc[1][4], a1, bv2); mma16(kvacc[1][5], a1, bv2 + 2);
            mma16(kvacc[1][6], a1, bv3); mma16(kvacc[1][7], a1, bv3 + 2);
            mma16(kvacc[1][8], a1, bv8);
        }
        __syncthreads();
    }
    float* g = g_kv + (size_t)bh * 256 * 72;
#pragma unroll
    for (int h = 0; h < 2; ++h)
#pragma unroll
        for (int ni = 0; ni < 9; ++ni) {
            int f0 = h * 128 + fb + qrow, d0 = ni * 8 + qc * 2;
            atomicAdd(g + f0 * 72 + d0, kvacc[h][ni][0]);
            atomicAdd(g + f0 * 72 + d0 + 1, kvacc[h][ni][1]);
            atomicAdd(g + (f0 + 8) * 72 + d0, kvacc[h][ni][2]);
            atomicAdd(g + (f0 + 8) * 72 + d0 + 1, kvacc[h][ni][3]);
        }
}

// ---------------------------------------------------------------------------
// favor_q: 128-row tiles, 8 warps x 16 rows, f in four 64-wide quarters.
// Per quarter: GEMM1 c[8][4] -> exp -> cu[4][4] -> GEMM3 drain into o[9][4].
// A-frags hoisted once per tile. No smem exchange; denom via shfl.
// ---------------------------------------------------------------------------
__global__ __launch_bounds__(256, 2) void favor_q(
    const float* __restrict__ Q_, const float* __restrict__ W_,
    float* __restrict__ O_) {
    extern __shared__ float s[];
    uint32_t* su = reinterpret_cast<uint32_t*>(s);
    __half* sh16 = reinterpret_cast<__half*>(s);
    const uint32_t sb = (uint32_t)__cvta_generic_to_shared(s);
    const int t = threadIdx.x, w = t >> 5, lane = t & 31;
    const int qrow = lane >> 2, qc = lane & 3;
    const int bh = blockIdx.x, bb = bh >> 4, hh = bh & 15;
#pragma unroll
    for (int i = 0; i < 16; ++i) {
        int idx = t + i * 256, f = idx >> 4, c4 = idx & 15;
        float4 wv = *reinterpret_cast<const float4*>(W_ + f * 64 + c4 * 4);
        *reinterpret_cast<uint2*>(su + QW + f * 36 + 2 * c4) =
            make_uint2(h2(wv.x, wv.y), h2(wv.z, wv.w));
    }
    {   // KV^T [d'][f] fp16, natural f order
        const float* g = g_kv + (size_t)bh * 256 * 72;
        for (int i = t; i < 256 * 72; i += 256) {
            int f = i / 72, d = i - f * 72;
            sh16[(QKV + d * 132) * 2 + f] = __float2half(g[i]);
        }
    }
    __syncthreads();
    const int ms = w * 16;
    const int lrow = lane & 15;
    const int khi = (lane >> 4) * 16;
    const int bko = (lane & 8) ? 16 : 0;
    const int brow = (lane & 7) + ((lane & 16) ? 8 : 0);
    const uint32_t aQ = sb + (QT + (ms + lrow) * 36) * 4 + khi;
    const uint32_t bW0 = sb + (QW + brow * 36) * 4 + bko;
    const uint32_t bK0 = sb + (QKV + brow * 132) * 4 + bko;
    const uint32_t bK80 = sb + (QKV + (64 + (lane & 7)) * 132) * 4 + bko;

    for (int ti = 0; ti < 8; ++ti) {
        const int l0 = ((int)blockIdx.y * 8 + ti) * 128;
#pragma unroll
        for (int i = 0; i < 8; ++i) {
            int idx = t + i * 256, l = idx >> 4, c4 = idx & 15;
            size_t off = ((size_t)(bb * L_ + l0 + l)) * D_ + hh * 64 + c4 * 4;
            float4 qq = *reinterpret_cast<const float4*>(Q_ + off);
            *reinterpret_cast<uint2*>(su + QT + l * 36 + 2 * c4) =
                make_uint2(h2(qq.x, qq.y), h2(qq.z, qq.w));
        }
        __syncthreads();
        // hoist GEMM1 A-frags (n-invariant) once per tile
        uint32_t a_all[4][4];
#pragma unroll
        for (int ks = 0; ks < 4; ++ks) ldsm4(a_all[ks], aQ + ks * 32);

        float o[9][4] = {};
#pragma unroll
        for (int fq = 0; fq < 4; ++fq) {
            const uint32_t bW = bW0 + fq * 9216;        // 64 W-rows = 64*36*4 B
            const uint32_t bK = bK0 + fq * 128;         // 64 f halfs = 128 B
            const uint32_t bK8 = bK80 + fq * 128;
            // ---- GEMM1: S(16m x 64n) for this quarter ----
            float c[8][4] = {};
#pragma unroll
            for (int ks = 0; ks < 4; ++ks) {
#pragma unroll
                for (int p = 0; p < 4; ++p) {
                    uint32_t bp[4];
                    ldsm4(bp, bW + p * 2304 + ks * 32);
                    mma16(c[2 * p], a_all[ks], bp);
                    mma16(c[2 * p + 1], a_all[ks], bp + 2);
                }
            }
            // ---- epilogue: exp + pack -> fp16 A-frags (k=16 each) ----
            uint32_t cu[4][4];
#pragma unroll
            for (int j = 0; j < 4; ++j) {
                float v00 = INVSQM * (__expf(SCALE * c[2 * j][0]) + CEPS);
                float v01 = INVSQM * (__expf(SCALE * c[2 * j][1]) + CEPS);
                float v02 = INVSQM * (__expf(SCALE * c[2 * j][2]) + CEPS);
                float v03 = INVSQM * (__expf(SCALE * c[2 * j][3]) + CEPS);
                float v10 = INVSQM * (__expf(SCALE * c[2 * j + 1][0]) + CEPS);
                float v11 = INVSQM * (__expf(SCALE * c[2 * j + 1][1]) + CEPS);
                float v12 = INVSQM * (__expf(SCALE * c[2 * j + 1][2]) + CEPS);
                float v13 = INVSQM * (__expf(SCALE * c[2 * j + 1][3]) + CEPS);
                cu[j][0] = h2(v00, v01);
                cu[j][1] = h2(v02, v03);
                cu[j][2] = h2(v10, v11);
                cu[j][3] = h2(v12, v13);
            }
            // ---- GEMM3: o += q'_quarter x KV^T_quarter ----
#pragma unroll
            for (int j = 0; j < 4; ++j) {
                uint32_t bv0[4], bv1[4], bv2[4], bv3[4], bv8[2];
                ldsm4(bv0, bK + j * 32);
                ldsm4(bv1, bK + 8448 + j * 32);
                ldsm4(bv2, bK + 16896 + j * 32);
                ldsm4(bv3, bK + 25344 + j * 32);
                ldsm2(bv8, bK8 + j * 32);
                mma16(o[0], cu[j], bv0); mma16(o[1], cu[j], bv0 + 2);
                mma16(o[2], cu[j], bv1); mma16(o[3], cu[j], bv1 + 2);
                mma16(o[4], cu[j], bv2); mma16(o[5], cu[j], bv2 + 2);
                mma16(o[6], cu[j], bv3); mma16(o[7], cu[j], bv3 + 2);
                mma16(o[8], cu[j], bv8);
            }
        }
        // ---- finish: denominator (col 64 = o[8] @ qc==0), divide, store ----
        float den0 = __shfl_sync(~0u, o[8][0], lane & ~3);
        float den1 = __shfl_sync(~0u, o[8][2], lane & ~3);
        if (fabsf(den0) <= CEPS) den0 += 2.f * CEPS;
        if (fabsf(den1) <= CEPS) den1 += 2.f * CEPS;
        float inv0 = 1.f / den0, inv1 = 1.f / den1;
        int r0 = ms + qrow;
        float* op0 = O_ + ((size_t)(bb * L_ + l0 + r0)) * D_ + hh * 64;
        float* op1 = op0 + 8 * D_;
#pragma unroll
        for (int ni = 0; ni < 8; ++ni) {
            int col = ni * 8 + 2 * qc;
            *reinterpret_cast<float2*>(op0 + col) =
                make_float2(o[ni][0] * inv0, o[ni][1] * inv0);
            *reinterpret_cast<float2*>(op1 + col) =
                make_float2(o[ni][2] * inv1, o[ni][3] * inv1);
        }
        __syncthreads();
    }
}

// ---------------------------------------------------------------------------
extern "C" void kernel_launch(void* const* d_in, const int* in_sizes, int n_in,
                              void* d_out, int out_size) {
    const float* q = (const float*)d_in[0];
    const float* k = (const float*)d_in[1];
    const float* v = (const float*)d_in[2];
    const float* w = (const float*)d_in[3];
    float* out = (float*)d_out;

    cudaFuncSetAttribute(favor_k, cudaFuncAttributeMaxDynamicSharedMemorySize, KFL * 4);
    cudaFuncSetAttribute(favor_q, cudaFuncAttributeMaxDynamicSharedMemorySize, QFL * 4);

    init_kernel<<<1, 1>>>();
    min_kernel<<<1024, 256>>>(k);
    favor_k<<<dim3(64, 8), 256, KFL * 4>>>(k, v, w);
    favor_q<<<dim3(64, 4), 256, QFL * 4>>>(q, w, out);
}